// round 1
// baseline (speedup 1.0000x reference)
#include <cuda_runtime.h>

// Problem constants
#define NL   8        // layers
#define NH   512      // hidden units per layer
#define NK   16       // fan-in per unit
#define NIN  512      // input width
#define NB   8192     // batch
#define NR   8        // batch rows per block
#define WTOT (NIN + NL*NH)   // 4608 total columns
#define VST  9               // smem column stride in floats (coprime with 32 banks)

// dynamic smem: values (4608*9*4 = 165888 B) + idx stage (32768 B) + w stage (32768 B)
#define SMEM_BYTES (WTOT*VST*4 + NH*NK*4 + NH*NK*4)   // 231424 <= 232448 (227KB)

__device__ __forceinline__ float fast_sigmoid(float z) {
    // 1/(1+exp(-z)) via fast ex2-based expf; ~1e-6 rel err, far under 1e-3 budget
    return 1.0f / (1.0f + __expf(-z));
}

__global__ __launch_bounds__(1024, 1)
void ffn_kernel(const float* __restrict__ x,
                const int*   __restrict__ link_idx,
                const float* __restrict__ weights,
                const float* __restrict__ bias,
                float*       __restrict__ out)
{
    extern __shared__ float smem[];
    float* vals  = smem;                                  // [WTOT][VST-padded] col-major, 8 rows
    int*   idx_s = (int*)  (smem + WTOT * VST);           // [NH][NK]
    float* w_s   = (float*)(idx_s + NH * NK);             // [NH][NK]

    const int tid  = threadIdx.x;
    const int lane = tid & 31;
    const int warp = tid >> 5;          // 0..31
    const int r    = lane & 7;          // batch row within tile (0..7)
    const int hsub = lane >> 3;         // 0..3
    const int r0   = blockIdx.x * NR;

    // ---- load x tile: rows r0..r0+7, cols 0..511 ----
    // consecutive threads -> consecutive c (global coalesced); smem stride 9 -> conflict-free
    #pragma unroll
    for (int i = tid; i < NR * NIN; i += 1024) {
        int rr = i >> 9;            // i / 512
        int c  = i & (NIN - 1);
        vals[c * VST + rr] = x[(long)(r0 + rr) * NIN + c];
    }

    int width = NIN;
    #pragma unroll 1
    for (int l = 0; l < NL; l++) {
        __syncthreads();   // prior layer's reads done -> safe to overwrite staging

        // ---- stage this layer's idx & weights (32KB each) into smem ----
        {
            const int4*   gi = (const int4*)  (link_idx + l * NH * NK);
            const float4* gw = (const float4*)(weights  + l * NH * NK);
            int4*   si = (int4*)  idx_s;
            float4* sw = (float4*)w_s;
            #pragma unroll
            for (int i = tid; i < (NH * NK) / 4; i += 1024) {  // 2048 elems, 2 iters
                si[i] = gi[i];
                sw[i] = gw[i];
            }
        }
        __syncthreads();

        const float* brow = bias + l * NH;

        #pragma unroll
        for (int p = 0; p < 4; p++) {
            const int h = p * 128 + warp * 4 + hsub;   // 128 h per pass, 4 passes

            // 8 lanes share h -> these LDS are broadcasts
            const int4*   si = (const int4*)  idx_s + h * 4;
            const float4* sw = (const float4*)w_s   + h * 4;
            int4   i0 = si[0], i1 = si[1], i2 = si[2], i3 = si[3];
            float4 w0 = sw[0], w1 = sw[1], w2 = sw[2], w3 = sw[3];

            float acc0 = __ldg(brow + h);
            float acc1 = 0.0f;

            // gathered values: 8-lane group reads 8 consecutive words of one column
            acc0 = fmaf(vals[i0.x * VST + r], w0.x, acc0);
            acc1 = fmaf(vals[i0.y * VST + r], w0.y, acc1);
            acc0 = fmaf(vals[i0.z * VST + r], w0.z, acc0);
            acc1 = fmaf(vals[i0.w * VST + r], w0.w, acc1);
            acc0 = fmaf(vals[i1.x * VST + r], w1.x, acc0);
            acc1 = fmaf(vals[i1.y * VST + r], w1.y, acc1);
            acc0 = fmaf(vals[i1.z * VST + r], w1.z, acc0);
            acc1 = fmaf(vals[i1.w * VST + r], w1.w, acc1);
            acc0 = fmaf(vals[i2.x * VST + r], w2.x, acc0);
            acc1 = fmaf(vals[i2.y * VST + r], w2.y, acc1);
            acc0 = fmaf(vals[i2.z * VST + r], w2.z, acc0);
            acc1 = fmaf(vals[i2.w * VST + r], w2.w, acc1);
            acc0 = fmaf(vals[i3.x * VST + r], w3.x, acc0);
            acc1 = fmaf(vals[i3.y * VST + r], w3.y, acc1);
            acc0 = fmaf(vals[i3.z * VST + r], w3.z, acc0);
            acc1 = fmaf(vals[i3.w * VST + r], w3.w, acc1);

            float o = fast_sigmoid(acc0 + acc1);

            // append new column (fresh col -> no intra-layer hazard)
            vals[(width + h) * VST + r] = o;

            if (l == NL - 1) {
                out[(long)(r0 + r) * NH + h] = o;
            }
        }
        width += NH;
    }
}

extern "C" void kernel_launch(void* const* d_in, const int* in_sizes, int n_in,
                              void* d_out, int out_size)
{
    const float* x        = (const float*)d_in[0];   // (8192, 512) f32
    const int*   link_idx = (const int*)  d_in[1];   // (8, 512, 16) i32
    const float* weights  = (const float*)d_in[2];   // (8, 512, 16) f32
    const float* bias     = (const float*)d_in[3];   // (8, 512) f32
    float*       out      = (float*)d_out;           // (8192, 512) f32

    cudaFuncSetAttribute(ffn_kernel,
                         cudaFuncAttributeMaxDynamicSharedMemorySize, SMEM_BYTES);

    ffn_kernel<<<NB / NR, 1024, SMEM_BYTES>>>(x, link_idx, weights, bias, out);
}

// round 3
// speedup vs baseline: 1.7497x; 1.7497x over previous
#include <cuda_runtime.h>
#include <cuda_fp16.h>

// Problem constants
#define NL   8        // layers
#define NH   512      // hidden units per layer
#define NK   16       // fan-in per unit
#define NIN  512      // input width
#define NB   8192     // batch
#define NR   16       // batch rows per block (8 row-pairs, half2 packed)
#define NRP  8        // row pairs
#define WSTORE (NIN + (NL-1)*NH)   // 4096 columns stored (layer-7 outputs go straight to out)
#define VST  9        // smem column stride in half2 words (coprime with 32 banks)

// dynamic smem bytes: values (4096*9*4 = 147456) + idx stage (32768) + w stage (32768)
#define SMEM_BYTES (WSTORE*VST*4 + NH*NK*4 + NH*NK*4)   // 212992

__device__ __forceinline__ float fast_sigmoid(float z) {
    return 1.0f / (1.0f + __expf(-z));
}

__global__ __launch_bounds__(1024, 1)
void ffn_kernel(const float* __restrict__ x,
                const int*   __restrict__ link_idx,
                const float* __restrict__ weights,
                const float* __restrict__ bias,
                float*       __restrict__ out)
{
    extern __shared__ __half2 smem2[];
    __half2* vals2 = smem2;                                   // [WSTORE][VST] col-major, 8 row-pairs
    int*     idx_s = (int*)  (smem2 + WSTORE * VST);          // [NH][NK]
    float*   w_s   = (float*)(idx_s + NH * NK);               // [NH][NK]

    const int tid  = threadIdx.x;
    const int lane = tid & 31;
    const int warp = tid >> 5;          // 0..31
    const int rp   = lane & 7;          // row-pair within tile (0..7) -> rows 2rp, 2rp+1
    const int hsub = lane >> 3;         // 0..3
    const int r0   = blockIdx.x * NR;

    // ---- load x tile: rows r0..r0+15, cols 0..511, packed as half2 (two rows per word) ----
    #pragma unroll
    for (int i = tid; i < NRP * NIN; i += 1024) {             // 4096 half2, 4 iters
        int pp = i >> 9;                // row pair 0..7
        int c  = i & (NIN - 1);
        float a = x[(long)(r0 + 2*pp    ) * NIN + c];
        float b = x[(long)(r0 + 2*pp + 1) * NIN + c];
        vals2[c * VST + pp] = __floats2half2_rn(a, b);
    }

    int width = NIN;
    #pragma unroll 1
    for (int l = 0; l < NL; l++) {
        __syncthreads();   // prior layer's reads done -> safe to overwrite staging

        // ---- stage this layer's idx & weights (32KB each) into smem ----
        {
            const int4*   gi = (const int4*)  (link_idx + l * NH * NK);
            const float4* gw = (const float4*)(weights  + l * NH * NK);
            int4*   si = (int4*)  idx_s;
            float4* sw = (float4*)w_s;
            #pragma unroll
            for (int i = tid; i < (NH * NK) / 4; i += 1024) {  // 2048 vec4, 2 iters
                si[i] = gi[i];
                sw[i] = gw[i];
            }
        }
        __syncthreads();

        const float* brow = bias + l * NH;
        const bool last = (l == NL - 1);

        #pragma unroll
        for (int p = 0; p < 4; p++) {
            const int h = p * 128 + warp * 4 + hsub;   // 128 h per pass, 4 passes

            // 8 lanes share h -> broadcast LDS.128
            const int4*   si = (const int4*)  idx_s + h * 4;
            const float4* sw = (const float4*)w_s   + h * 4;
            int4   i0 = si[0], i1 = si[1], i2 = si[2], i3 = si[3];
            float4 w0 = sw[0], w1 = sw[1], w2 = sw[2], w3 = sw[3];

            float b0 = __ldg(brow + h);
            float ax0 = b0,   ay0 = b0;     // bias for BOTH rows of the pair (R2 bug: ay0 was 0)
            float ax1 = 0.0f, ay1 = 0.0f;

#define GATHER0(idx, w) { float2 f = __half22float2(vals2[(idx) * VST + rp]); \
                          ax0 = fmaf(f.x, (w), ax0); ay0 = fmaf(f.y, (w), ay0); }
#define GATHER1(idx, w) { float2 f = __half22float2(vals2[(idx) * VST + rp]); \
                          ax1 = fmaf(f.x, (w), ax1); ay1 = fmaf(f.y, (w), ay1); }
            GATHER0(i0.x, w0.x); GATHER1(i0.y, w0.y);
            GATHER0(i0.z, w0.z); GATHER1(i0.w, w0.w);
            GATHER0(i1.x, w1.x); GATHER1(i1.y, w1.y);
            GATHER0(i1.z, w1.z); GATHER1(i1.w, w1.w);
            GATHER0(i2.x, w2.x); GATHER1(i2.y, w2.y);
            GATHER0(i2.z, w2.z); GATHER1(i2.w, w2.w);
            GATHER0(i3.x, w3.x); GATHER1(i3.y, w3.y);
            GATHER0(i3.z, w3.z); GATHER1(i3.w, w3.w);
#undef GATHER0
#undef GATHER1

            float ox = fast_sigmoid(ax0 + ax1);
            float oy = fast_sigmoid(ay0 + ay1);

            if (!last) {
                vals2[(width + h) * VST + rp] = __floats2half2_rn(ox, oy);
            } else {
                // write final layer straight from fp32 (no storage quantization)
                out[(long)(r0 + 2*rp    ) * NH + h] = ox;
                out[(long)(r0 + 2*rp + 1) * NH + h] = oy;
            }
        }
        width += NH;
    }
}

extern "C" void kernel_launch(void* const* d_in, const int* in_sizes, int n_in,
                              void* d_out, int out_size)
{
    const float* x        = (const float*)d_in[0];   // (8192, 512) f32
    const int*   link_idx = (const int*)  d_in[1];   // (8, 512, 16) i32
    const float* weights  = (const float*)d_in[2];   // (8, 512, 16) f32
    const float* bias     = (const float*)d_in[3];   // (8, 512) f32
    float*       out      = (float*)d_out;           // (8192, 512) f32

    cudaFuncSetAttribute(ffn_kernel,
                         cudaFuncAttributeMaxDynamicSharedMemorySize, SMEM_BYTES);

    ffn_kernel<<<NB / NR, 1024, SMEM_BYTES>>>(x, link_idx, weights, bias, out);
}